// round 5
// baseline (speedup 1.0000x reference)
#include <cuda_runtime.h>

// CharRNN: 3-layer tanh RNN, B=512, T=1024, HID=100, VOCAB=62.
// R5: 512 threads (16 warps, occ 25%), in-warp 4-way k-split (p=lane>>3,
//     m=lane&7; conflict-free stride-100 rows; shfl reduction), smem weights
//     (no big reg arrays -> no spills), double-buffered h, 3 barriers/step,
//     decoder (reg W_dec quarter, 28 regs) on warps 8..15 merged into phase A.

#define BB    512
#define TT    1024
#define HID   100
#define VOCAB 62
#define NL    3
#define ROWS  4
#define NCTA  (BB / ROWS)       // 128
#define NTHR  512

// ---- shared memory layout (floats), all rows stride HID=100 ----
#define OFF_WH1  0
#define OFF_WI2  10000
#define OFF_WH2  20000
#define OFF_WI3  30000
#define OFF_WH3  40000
#define OFF_H    50000          // [2 buf][NL][ROWS][HID]
#define SMEM_FLOATS (OFF_H + 2 * NL * ROWS * HID)   // 52,400 -> 209,600 B

__device__ float g_table[VOCAB * HID];  // emb@Wi1^T + b_ih1 + b_hh1

// ---------------------------------------------------------------------------
__global__ void table_kernel(const float* __restrict__ emb,
                             const float* __restrict__ W_ih,
                             const float* __restrict__ b_ih,
                             const float* __restrict__ b_hh) {
    int v = blockIdx.x;
    int j = threadIdx.x;
    if (j >= HID) return;
    float acc = b_ih[j] + b_hh[j];
    const float* e = emb + v * HID;
    const float* w = W_ih + j * HID;
#pragma unroll
    for (int k = 0; k < HID; k++) acc += e[k] * w[k];
    g_table[v * HID + j] = acc;
}

// ---------------------------------------------------------------------------
__device__ __forceinline__ void fma2(unsigned long long& acc,
                                     unsigned long long a,
                                     unsigned long long b) {
    asm("fma.rn.f32x2 %0, %1, %2, %3;" : "=l"(acc) : "l"(a), "l"(b), "l"(acc));
}
__device__ __forceinline__ float hadd2(unsigned long long a) {
    float lo = __uint_as_float((unsigned)a);
    float hi = __uint_as_float((unsigned)(a >> 32));
    return lo + hi;
}
__device__ __forceinline__ ulonglong2 ldv(const float* pf) {
    return *reinterpret_cast<const ulonglong2*>(pf);
}
__device__ __forceinline__ float tanho(float x) {
    float e = __expf(2.0f * x);
    return 1.0f - __fdividef(2.0f, e + 1.0f);
}
// full k-quarter reduction: sum over the 4 p-groups (lane bits 3,4)
__device__ __forceinline__ float redq(unsigned long long a) {
    float v = hadd2(a);
    v += __shfl_xor_sync(0xffffffffu, v, 8);
    v += __shfl_xor_sync(0xffffffffu, v, 16);
    return v;
}

// ---------------------------------------------------------------------------
__global__ __launch_bounds__(NTHR, 1)
void rnn_kernel(const int*   __restrict__ ids,
                const float* __restrict__ W_ih,
                const float* __restrict__ W_hh,
                const float* __restrict__ b_ih,
                const float* __restrict__ b_hh,
                const float* __restrict__ W_dec,
                const float* __restrict__ b_dec,
                float* __restrict__ logits,
                float* __restrict__ hidden) {
    extern __shared__ float s[];
    const int tid  = threadIdx.x;
    const int wid  = tid >> 5;
    const int lane = tid & 31;
    const int p    = lane >> 3;        // k-quarter: 0..3
    const int m    = lane & 7;         // neuron slot within warp
    const int b0   = blockIdx.x * ROWS;
    const int kh   = p * 28;           // quarter float offset (p=3 -> 84, 4 chunks)

    const int  j1    = wid * 8 + m;                     // layer neuron slot
    const int  j1c   = (j1 < HID) ? j1 : (HID - 1);
    const bool l1act = (wid < 13);                      // warps doing layer dots
    const bool hwr   = (p == 0) && (j1 < HID);          // h writer lanes

    const int  jd    = (wid - 8) * 8 + m;               // decoder neuron (warps 8..15)
    const bool dact  = (wid >= 8);
    const int  jdc   = (jd >= 0 && jd < VOCAB) ? jd : 0;
    const bool dwr   = dact && (p == 0) && (jd < VOCAB);

    // ---- stage weights into smem ----
    for (int i = tid; i < HID * HID; i += NTHR) {
        s[OFF_WH1 + i] = W_hh[i];
        s[OFF_WI2 + i] = W_ih[1 * HID * HID + i];
        s[OFF_WH2 + i] = W_hh[1 * HID * HID + i];
        s[OFF_WI3 + i] = W_ih[2 * HID * HID + i];
        s[OFF_WH3 + i] = W_hh[2 * HID * HID + i];
    }
    for (int i = tid; i < 2 * NL * ROWS * HID; i += NTHR) s[OFF_H + i] = 0.0f;

    // ---- W_dec quarter in registers (28 regs max; no spill risk) ----
    ulonglong2 wdr[7];
    {
        const float* src = W_dec + jdc * HID + kh;
        const int nv = (p < 3) ? 7 : 4;
#pragma unroll
        for (int kc = 0; kc < 7; kc++)
            wdr[kc] = (kc < nv) ? ldv(src + 4 * kc) : make_ulonglong2(0, 0);
    }
    const float b2r = b_ih[1 * HID + j1c] + b_hh[1 * HID + j1c];
    const float b3r = b_ih[2 * HID + j1c] + b_hh[2 * HID + j1c];
    const float bdr = b_dec[jdc];

    const float* wh1row = s + OFF_WH1 + j1c * HID + kh;
    const float* wi2row = s + OFF_WI2 + j1c * HID + kh;
    const float* wh2row = s + OFF_WH2 + j1c * HID + kh;
    const float* wi3row = s + OFF_WI3 + j1c * HID + kh;
    const float* wh3row = s + OFF_WH3 + j1c * HID + kh;

    int tok[ROWS];
#pragma unroll
    for (int r = 0; r < ROWS; r++) tok[r] = ids[(b0 + r) * TT];

    __syncthreads();

    for (int t = 0; t < TT; t++) {
        const int ro = t & 1, wo = ro ^ 1;
        const float* h1o = s + OFF_H + (ro * NL + 0) * ROWS * HID;
        const float* h2o = s + OFF_H + (ro * NL + 1) * ROWS * HID;
        const float* h3o = s + OFF_H + (ro * NL + 2) * ROWS * HID;
        float* h1n = s + OFF_H + (wo * NL + 0) * ROWS * HID;
        float* h2n = s + OFF_H + (wo * NL + 1) * ROWS * HID;
        float* h3n = s + OFF_H + (wo * NL + 2) * ROWS * HID;

        // ========= phase A: layer-1(t) + decoder(t-1) =========
        if (l1act) {
            float tbl[ROWS];
#pragma unroll
            for (int r = 0; r < ROWS; r++) tbl[r] = g_table[tok[r] * HID + j1c];

            unsigned long long a[ROWS] = {0, 0, 0, 0};
#pragma unroll
            for (int kc = 0; kc < 4; kc++) {
                ulonglong2 w = ldv(wh1row + 4 * kc);
#pragma unroll
                for (int r = 0; r < ROWS; r++) {
                    ulonglong2 h = ldv(h1o + r * HID + kh + 4 * kc);
                    fma2(a[r], w.x, h.x); fma2(a[r], w.y, h.y);
                }
            }
            if (p < 3) {
#pragma unroll
                for (int kc = 4; kc < 7; kc++) {
                    ulonglong2 w = ldv(wh1row + 4 * kc);
#pragma unroll
                    for (int r = 0; r < ROWS; r++) {
                        ulonglong2 h = ldv(h1o + r * HID + kh + 4 * kc);
                        fma2(a[r], w.x, h.x); fma2(a[r], w.y, h.y);
                    }
                }
            }
#pragma unroll
            for (int r = 0; r < ROWS; r++) {
                float sv = redq(a[r]);
                if (hwr) h1n[r * HID + j1] = tanho(tbl[r] + sv);
            }
        }
        if (dact) {
            unsigned long long a[ROWS] = {0, 0, 0, 0};
#pragma unroll
            for (int kc = 0; kc < 4; kc++) {
                ulonglong2 w = wdr[kc];
#pragma unroll
                for (int r = 0; r < ROWS; r++) {
                    ulonglong2 h = ldv(h3o + r * HID + kh + 4 * kc);
                    fma2(a[r], w.x, h.x); fma2(a[r], w.y, h.y);
                }
            }
            if (p < 3) {
#pragma unroll
                for (int kc = 4; kc < 7; kc++) {
                    ulonglong2 w = wdr[kc];
#pragma unroll
                    for (int r = 0; r < ROWS; r++) {
                        ulonglong2 h = ldv(h3o + r * HID + kh + 4 * kc);
                        fma2(a[r], w.x, h.x); fma2(a[r], w.y, h.y);
                    }
                }
            }
#pragma unroll
            for (int r = 0; r < ROWS; r++) {
                float sv = redq(a[r]);
                if (dwr && t > 0)
                    logits[((size_t)(b0 + r) * TT + (t - 1)) * VOCAB + jd] = bdr + sv;
            }
        }
        __syncthreads();

        // ========= phase B: layer-2 =========
        if (l1act) {
            unsigned long long a[ROWS] = {0, 0, 0, 0};
#pragma unroll
            for (int kc = 0; kc < 4; kc++) {
                ulonglong2 wi = ldv(wi2row + 4 * kc);
                ulonglong2 wh = ldv(wh2row + 4 * kc);
#pragma unroll
                for (int r = 0; r < ROWS; r++) {
                    ulonglong2 hx = ldv(h1n + r * HID + kh + 4 * kc);
                    ulonglong2 hh = ldv(h2o + r * HID + kh + 4 * kc);
                    fma2(a[r], wi.x, hx.x); fma2(a[r], wi.y, hx.y);
                    fma2(a[r], wh.x, hh.x); fma2(a[r], wh.y, hh.y);
                }
            }
            if (p < 3) {
#pragma unroll
                for (int kc = 4; kc < 7; kc++) {
                    ulonglong2 wi = ldv(wi2row + 4 * kc);
                    ulonglong2 wh = ldv(wh2row + 4 * kc);
#pragma unroll
                    for (int r = 0; r < ROWS; r++) {
                        ulonglong2 hx = ldv(h1n + r * HID + kh + 4 * kc);
                        ulonglong2 hh = ldv(h2o + r * HID + kh + 4 * kc);
                        fma2(a[r], wi.x, hx.x); fma2(a[r], wi.y, hx.y);
                        fma2(a[r], wh.x, hh.x); fma2(a[r], wh.y, hh.y);
                    }
                }
            }
#pragma unroll
            for (int r = 0; r < ROWS; r++) {
                float sv = redq(a[r]);
                if (hwr) h2n[r * HID + j1] = tanho(b2r + sv);
            }
        }
        __syncthreads();

        // ========= phase C: layer-3 + next-token prefetch =========
        {
            const int tn = (t + 1 < TT) ? (t + 1) : t;
#pragma unroll
            for (int r = 0; r < ROWS; r++) tok[r] = ids[(b0 + r) * TT + tn];
        }
        if (l1act) {
            unsigned long long a[ROWS] = {0, 0, 0, 0};
#pragma unroll
            for (int kc = 0; kc < 4; kc++) {
                ulonglong2 wi = ldv(wi3row + 4 * kc);
                ulonglong2 wh = ldv(wh3row + 4 * kc);
#pragma unroll
                for (int r = 0; r < ROWS; r++) {
                    ulonglong2 hx = ldv(h2n + r * HID + kh + 4 * kc);
                    ulonglong2 hh = ldv(h3o + r * HID + kh + 4 * kc);
                    fma2(a[r], wi.x, hx.x); fma2(a[r], wi.y, hx.y);
                    fma2(a[r], wh.x, hh.x); fma2(a[r], wh.y, hh.y);
                }
            }
            if (p < 3) {
#pragma unroll
                for (int kc = 4; kc < 7; kc++) {
                    ulonglong2 wi = ldv(wi3row + 4 * kc);
                    ulonglong2 wh = ldv(wh3row + 4 * kc);
#pragma unroll
                    for (int r = 0; r < ROWS; r++) {
                        ulonglong2 hx = ldv(h2n + r * HID + kh + 4 * kc);
                        ulonglong2 hh = ldv(h3o + r * HID + kh + 4 * kc);
                        fma2(a[r], wi.x, hx.x); fma2(a[r], wi.y, hx.y);
                        fma2(a[r], wh.x, hh.x); fma2(a[r], wh.y, hh.y);
                    }
                }
            }
#pragma unroll
            for (int r = 0; r < ROWS; r++) {
                float sv = redq(a[r]);
                if (hwr) h3n[r * HID + j1] = tanho(b3r + sv);
            }
        }
        __syncthreads();
    }

    // ---- final decoder for t = TT-1 (final h3 lives in buffer 0) ----
    if (dact) {
        const float* h3f = s + OFF_H + (0 * NL + 2) * ROWS * HID;
        unsigned long long a[ROWS] = {0, 0, 0, 0};
#pragma unroll
        for (int kc = 0; kc < 4; kc++) {
            ulonglong2 w = wdr[kc];
#pragma unroll
            for (int r = 0; r < ROWS; r++) {
                ulonglong2 h = ldv(h3f + r * HID + kh + 4 * kc);
                fma2(a[r], w.x, h.x); fma2(a[r], w.y, h.y);
            }
        }
        if (p < 3) {
#pragma unroll
            for (int kc = 4; kc < 7; kc++) {
                ulonglong2 w = wdr[kc];
#pragma unroll
                for (int r = 0; r < ROWS; r++) {
                    ulonglong2 h = ldv(h3f + r * HID + kh + 4 * kc);
                    fma2(a[r], w.x, h.x); fma2(a[r], w.y, h.y);
                }
            }
        }
#pragma unroll
        for (int r = 0; r < ROWS; r++) {
            float sv = redq(a[r]);
            if (dwr)
                logits[((size_t)(b0 + r) * TT + (TT - 1)) * VOCAB + jd] = bdr + sv;
        }
    }

    // ---- final hidden states [NL, B, HID] (buffer 0) ----
    if (hwr) {
#pragma unroll
        for (int l = 0; l < NL; l++) {
            const float* hf = s + OFF_H + (0 * NL + l) * ROWS * HID;
#pragma unroll
            for (int r = 0; r < ROWS; r++)
                hidden[(size_t)(l * BB + b0 + r) * HID + j1] = hf[r * HID + j1];
        }
    }
}

// ---------------------------------------------------------------------------
extern "C" void kernel_launch(void* const* d_in, const int* in_sizes, int n_in,
                              void* d_out, int out_size) {
    const int*   ids   = (const int*)  d_in[0];
    const float* emb   = (const float*)d_in[1];
    const float* W_ih  = (const float*)d_in[2];
    const float* W_hh  = (const float*)d_in[3];
    const float* b_ih  = (const float*)d_in[4];
    const float* b_hh  = (const float*)d_in[5];
    const float* W_dec = (const float*)d_in[6];
    const float* b_dec = (const float*)d_in[7];

    float* out    = (float*)d_out;
    float* logits = out;
    float* hidden = out + ((size_t)out_size - (size_t)NL * BB * HID);

    table_kernel<<<VOCAB, 128>>>(emb, W_ih, b_ih, b_hh);

    size_t smem = SMEM_FLOATS * sizeof(float);
    cudaFuncSetAttribute(rnn_kernel, cudaFuncAttributeMaxDynamicSharedMemorySize,
                         (int)smem);
    rnn_kernel<<<NCTA, NTHR, smem>>>(ids, W_ih, W_hh, b_ih, b_hh,
                                     W_dec, b_dec, logits, hidden);
}